// round 12
// baseline (speedup 1.0000x reference)
#include <cuda_runtime.h>

#define DD 8
#define HH 64
#define TPB 256
#define RPC 256   // rows per CTA (8 warps x 32 rows)

// ---- dynamic shared memory layout (float offsets; all 16B aligned) ----
#define OW1T 0        // [9][64]   W1^T ([d][j]; d==8 is t row)
#define OB1  576      // [64]
#define OW2T 640      // [64][64]  W2^T ([k][j]) forward
#define OW2  4736     // [64][64]  W2   ([j][k]) backward
#define OB2  8832     // [64]
#define OW3T 8896     // [64][8]   W3^T ([k][d])
#define OB3  9408     // [8] (+8 pad)
#define OW1S 9424     // [64] sum_{d<8} W1[k][d]
#define OW3S 9488     // [64] sum_d W3[d][j]
#define OX   9552     // [8][RPC]  x state ([d][row])
#define OH   11600    // [64][RPC] h1 state ([col][row])
#define OG   27984    // [64][RPC] h2 / g_a2 state ([col][row])
#define SMEM_FLOATS 44368
#define SMEM_BYTES  (SMEM_FLOATS * 4)   // 177472 B

typedef unsigned long long u64;
typedef ulonglong2 u64x2;

__device__ __forceinline__ u64 pk2(float a, float b) {
    u64 r; asm("mov.b64 %0, {%1,%2};" : "=l"(r) : "f"(a), "f"(b)); return r;
}
__device__ __forceinline__ void up2(u64 v, float& a, float& b) {
    asm("mov.b64 {%0,%1}, %2;" : "=f"(a), "=f"(b) : "l"(v));
}
__device__ __forceinline__ u64 f2fma(u64 a, u64 b, u64 c) {
    u64 d; asm("fma.rn.f32x2 %0, %1, %2, %3;" : "=l"(d) : "l"(a), "l"(b), "l"(c)); return d;
}
// tanh(x) = 1 - 2/(exp2(2*log2e*x)+1); saturates correctly, ~1e-6 rel err.
__device__ __forceinline__ float fast_tanh(float x) {
    float e; asm("ex2.approx.f32 %0, %1;" : "=f"(e) : "f"(x * 2.88539008177792681472f));
    float r; asm("rcp.approx.f32 %0, %1;" : "=f"(r) : "f"(e + 1.0f));
    return fmaf(-2.0f, r, 1.0f);
}

// 8 packed FMAs for one row's broadcast P against 16 weights (4 u64x2)
#define ROW8(R, P, W0, W1, W2c, W3c) \
    acc[R][0]=f2fma(P,(W0).x,acc[R][0]); acc[R][1]=f2fma(P,(W0).y,acc[R][1]); \
    acc[R][2]=f2fma(P,(W1).x,acc[R][2]); acc[R][3]=f2fma(P,(W1).y,acc[R][3]); \
    acc[R][4]=f2fma(P,(W2c).x,acc[R][4]); acc[R][5]=f2fma(P,(W2c).y,acc[R][5]); \
    acc[R][6]=f2fma(P,(W3c).x,acc[R][6]); acc[R][7]=f2fma(P,(W3c).y,acc[R][7]);

// k-loop body: A = state[SRCOFF][k][rowb..rowb+3] (LDS.128 broadcast),
// W = dsm[WOFF + k*64 + colb .. +15] (4x LDS.128), 32 f2fma
#define MVK(SRCOFF, WOFF, KN) \
    _Pragma("unroll 4") \
    for (int k = 0; k < (KN); k++) { \
        const float4 av = *(const float4*)&dsm[(SRCOFF) + k * RPC + rowb]; \
        const u64 p0 = pk2(av.x, av.x), p1 = pk2(av.y, av.y); \
        const u64 p2 = pk2(av.z, av.z), p3 = pk2(av.w, av.w); \
        const u64* wp = (const u64*)&dsm[(WOFF) + k * HH + colb]; \
        const u64x2 w0 = *(const u64x2*)(wp); \
        const u64x2 w1 = *(const u64x2*)(wp + 2); \
        const u64x2 w2 = *(const u64x2*)(wp + 4); \
        const u64x2 w3 = *(const u64x2*)(wp + 6); \
        ROW8(0, p0, w0, w1, w2, w3) \
        ROW8(1, p1, w0, w1, w2, w3) \
        ROW8(2, p2, w0, w1, w2, w3) \
        ROW8(3, p3, w0, w1, w2, w3) \
    }

// init 4x8 accumulators from a 16-wide bias slice (replicated across rows)
#define MV_BIASINIT(BOFF) \
    { const u64* bp = (const u64*)&dsm[(BOFF) + colb]; \
      const u64x2 b0 = *(const u64x2*)(bp), b1 = *(const u64x2*)(bp + 2); \
      const u64x2 b2 = *(const u64x2*)(bp + 4), b3 = *(const u64x2*)(bp + 6); \
      _Pragma("unroll") \
      for (int rr = 0; rr < 4; rr++) { \
          acc[rr][0] = b0.x; acc[rr][1] = b0.y; acc[rr][2] = b1.x; acc[rr][3] = b1.y; \
          acc[rr][4] = b2.x; acc[rr][5] = b2.y; acc[rr][6] = b3.x; acc[rr][7] = b3.y; } }

// tanh + transposed writeback: per colpair, 8 values -> 2 STS.128 columns
#define WB_TANH(OFF) \
    _Pragma("unroll") \
    for (int cp = 0; cp < 8; cp++) { \
        float e0,o0,e1,o1,e2,o2,e3,o3; \
        up2(acc[0][cp], e0, o0); up2(acc[1][cp], e1, o1); \
        up2(acc[2][cp], e2, o2); up2(acc[3][cp], e3, o3); \
        e0 = fast_tanh(e0); o0 = fast_tanh(o0); e1 = fast_tanh(e1); o1 = fast_tanh(o1); \
        e2 = fast_tanh(e2); o2 = fast_tanh(o2); e3 = fast_tanh(e3); o3 = fast_tanh(o3); \
        *(float4*)&dsm[(OFF) + (colb + 2*cp) * RPC + rowb]     = make_float4(e0,e1,e2,e3); \
        *(float4*)&dsm[(OFF) + (colb + 2*cp + 1) * RPC + rowb] = make_float4(o0,o1,o2,o3); \
    }

__global__ void __launch_bounds__(TPB, 1)
cnf_kernel(const float* __restrict__ x0,
           const float* __restrict__ W1g,   // [64][9]
           const float* __restrict__ b1g,   // [64]
           const float* __restrict__ W2g,   // [64][64]
           const float* __restrict__ b2g,   // [64]
           const float* __restrict__ W3g,   // [8][64]
           const float* __restrict__ b3g,   // [8]
           const int*   __restrict__ nsp,
           float* __restrict__ out, int n)
{
    extern __shared__ float dsm[];
    const int tid = threadIdx.x;

    // ---------------- cooperative weight init ----------------
    for (int idx = tid; idx < HH * HH; idx += TPB) {
        int j = idx >> 6, k = idx & 63;
        float v = W2g[idx];
        dsm[OW2 + j * HH + k]  = v;   // [j][k]
        dsm[OW2T + k * HH + j] = v;   // [k][j]
    }
    for (int idx = tid; idx < HH * (DD + 1); idx += TPB) {
        int j = idx / (DD + 1), d = idx % (DD + 1);
        dsm[OW1T + d * HH + j] = W1g[idx];
    }
    for (int idx = tid; idx < HH * DD; idx += TPB) {
        int d = idx >> 6, k = idx & 63;
        dsm[OW3T + k * DD + d] = W3g[idx];
    }
    for (int idx = tid; idx < HH; idx += TPB) {
        dsm[OB1 + idx] = b1g[idx];
        dsm[OB2 + idx] = b2g[idx];
        float s1 = 0.f;
        for (int d = 0; d < DD; d++) s1 += W1g[idx * (DD + 1) + d];
        dsm[OW1S + idx] = s1;
        float s3 = 0.f;
        for (int d = 0; d < DD; d++) s3 += W3g[d * HH + idx];
        dsm[OW3S + idx] = s3;
    }
    if (tid < DD) dsm[OB3 + tid] = b3g[tid];

    // ---------------- x state init ([d][row] transposed) ----------------
    const int base = blockIdx.x * RPC;
    for (int idx = tid; idx < RPC * DD; idx += TPB) {
        int rr = idx >> 3, d = idx & 7;
        int grow = base + rr;
        dsm[OX + d * RPC + rr] = (grow < n) ? x0[grow * DD + d] : 0.f;
    }
    __syncthreads();

    // warp tile coordinates
    const int lane = tid & 31;
    const int warp = tid >> 5;
    const int r4   = lane >> 2;       // 0..7
    const int cq   = lane & 3;        // 0..3
    const int rowb = warp * 32 + r4 * 4;   // first of this thread's 4 rows (CTA-local)
    const int colb = cq * 16;              // first of this thread's 16 cols

    const int nsteps = nsp ? *nsp : 100;
    const float dt = 1.0f / (float)nsteps;

    float ldr0 = 0.f, ldr1 = 0.f, ldr2 = 0.f, ldr3 = 0.f;

    #pragma unroll 1
    for (int i = 0; i < nsteps; i++) {
        const float t = (float)i * dt;

        #pragma unroll 1
        for (int pass = 0; pass < 2; pass++) {
            // ---- layer 1: OH = tanh(W1 @ [x; t] + b1) ----
            {
                u64 acc[4][8];
                MV_BIASINIT(OB1)
                MVK(OX, OW1T, 8)
                {   // t row (d == 8): same broadcast for all rows
                    const u64 pt = pk2(t, t);
                    const u64* wp = (const u64*)&dsm[OW1T + 8 * HH + colb];
                    const u64x2 w0 = *(const u64x2*)(wp);
                    const u64x2 w1 = *(const u64x2*)(wp + 2);
                    const u64x2 w2 = *(const u64x2*)(wp + 4);
                    const u64x2 w3 = *(const u64x2*)(wp + 6);
                    ROW8(0, pt, w0, w1, w2, w3)
                    ROW8(1, pt, w0, w1, w2, w3)
                    ROW8(2, pt, w0, w1, w2, w3)
                    ROW8(3, pt, w0, w1, w2, w3)
                }
                WB_TANH(OH)
            }
            __syncwarp();

            // ---- layer 2 ----
            if (pass == 0) {
                // OG = tanh(W2 @ h1 + b2)
                u64 acc[4][8];
                MV_BIASINIT(OB2)
                MVK(OH, OW2T, 64)
                WB_TANH(OG)
            } else {
                // fused: g = tanh(...); OG = w3s * (1 - g^2)  (g_a2 for VJP)
                u64 acc[4][8];
                MV_BIASINIT(OB2)
                MVK(OH, OW2T, 64)
                #pragma unroll
                for (int cp = 0; cp < 8; cp++) {
                    const float wze = dsm[OW3S + colb + 2*cp];
                    const float wzo = dsm[OW3S + colb + 2*cp + 1];
                    float e0,o0,e1,o1,e2,o2,e3,o3;
                    up2(acc[0][cp], e0, o0); up2(acc[1][cp], e1, o1);
                    up2(acc[2][cp], e2, o2); up2(acc[3][cp], e3, o3);
                    e0 = fast_tanh(e0); o0 = fast_tanh(o0); e1 = fast_tanh(e1); o1 = fast_tanh(o1);
                    e2 = fast_tanh(e2); o2 = fast_tanh(o2); e3 = fast_tanh(e3); o3 = fast_tanh(o3);
                    e0 = fmaf(-(e0 * wze), e0, wze); e1 = fmaf(-(e1 * wze), e1, wze);
                    e2 = fmaf(-(e2 * wze), e2, wze); e3 = fmaf(-(e3 * wze), e3, wze);
                    o0 = fmaf(-(o0 * wzo), o0, wzo); o1 = fmaf(-(o1 * wzo), o1, wzo);
                    o2 = fmaf(-(o2 * wzo), o2, wzo); o3 = fmaf(-(o3 * wzo), o3, wzo);
                    *(float4*)&dsm[OG + (colb + 2*cp) * RPC + rowb]     = make_float4(e0,e1,e2,e3);
                    *(float4*)&dsm[OG + (colb + 2*cp + 1) * RPC + rowb] = make_float4(o0,o1,o2,o3);
                }
            }
            __syncwarp();

            // ---- layer 3 (pass 0 only): x += dt * (W3 @ h2 + b3) ----
            if (pass == 0) {
                u64 ac[4][4];
                {
                    const u64x2 b0 = *(const u64x2*)&dsm[OB3];
                    const u64x2 b1 = *(const u64x2*)&dsm[OB3 + 4];
                    #pragma unroll
                    for (int rr = 0; rr < 4; rr++) {
                        ac[rr][0] = b0.x; ac[rr][1] = b0.y;
                        ac[rr][2] = b1.x; ac[rr][3] = b1.y;
                    }
                }
                #pragma unroll 4
                for (int k = 0; k < HH; k++) {
                    const float4 av = *(const float4*)&dsm[OG + k * RPC + rowb];
                    const u64 p0 = pk2(av.x, av.x), p1 = pk2(av.y, av.y);
                    const u64 p2 = pk2(av.z, av.z), p3 = pk2(av.w, av.w);
                    const u64x2 w0 = *(const u64x2*)&dsm[OW3T + k * DD];
                    const u64x2 w1 = *(const u64x2*)&dsm[OW3T + k * DD + 4];
                    ac[0][0]=f2fma(p0,w0.x,ac[0][0]); ac[0][1]=f2fma(p0,w0.y,ac[0][1]);
                    ac[0][2]=f2fma(p0,w1.x,ac[0][2]); ac[0][3]=f2fma(p0,w1.y,ac[0][3]);
                    ac[1][0]=f2fma(p1,w0.x,ac[1][0]); ac[1][1]=f2fma(p1,w0.y,ac[1][1]);
                    ac[1][2]=f2fma(p1,w1.x,ac[1][2]); ac[1][3]=f2fma(p1,w1.y,ac[1][3]);
                    ac[2][0]=f2fma(p2,w0.x,ac[2][0]); ac[2][1]=f2fma(p2,w0.y,ac[2][1]);
                    ac[2][2]=f2fma(p2,w1.x,ac[2][2]); ac[2][3]=f2fma(p2,w1.y,ac[2][3]);
                    ac[3][0]=f2fma(p3,w0.x,ac[3][0]); ac[3][1]=f2fma(p3,w0.y,ac[3][1]);
                    ac[3][2]=f2fma(p3,w1.x,ac[3][2]); ac[3][3]=f2fma(p3,w1.y,ac[3][3]);
                }
                if (cq == 0) {
                    float dxf[4][8];
                    #pragma unroll
                    for (int rr = 0; rr < 4; rr++) {
                        up2(ac[rr][0], dxf[rr][0], dxf[rr][1]);
                        up2(ac[rr][1], dxf[rr][2], dxf[rr][3]);
                        up2(ac[rr][2], dxf[rr][4], dxf[rr][5]);
                        up2(ac[rr][3], dxf[rr][6], dxf[rr][7]);
                    }
                    #pragma unroll
                    for (int d = 0; d < DD; d++) {
                        float4 cur = *(const float4*)&dsm[OX + d * RPC + rowb];
                        cur.x = fmaf(dt, dxf[0][d], cur.x);
                        cur.y = fmaf(dt, dxf[1][d], cur.y);
                        cur.z = fmaf(dt, dxf[2][d], cur.z);
                        cur.w = fmaf(dt, dxf[3][d], cur.w);
                        *(float4*)&dsm[OX + d * RPC + rowb] = cur;
                    }
                }
                __syncwarp();
            }
        }

        // ---- backward matvec: gh1[k] = sum_j g_a2[j] * W2[j][k]; fold into ld ----
        {
            u64 acc[4][8];
            #pragma unroll
            for (int rr = 0; rr < 4; rr++)
                #pragma unroll
                for (int jj = 0; jj < 8; jj++) acc[rr][jj] = 0ull;
            MVK(OG, OW2, 64)

            float p0 = 0.f, p1 = 0.f, p2 = 0.f, p3 = 0.f;
            #pragma unroll
            for (int cp = 0; cp < 8; cp++) {
                const int k0 = colb + 2 * cp;
                const float w1e = dsm[OW1S + k0];
                const float w1o = dsm[OW1S + k0 + 1];
                const float4 he = *(const float4*)&dsm[OH + k0 * RPC + rowb];
                const float4 ho = *(const float4*)&dsm[OH + (k0 + 1) * RPC + rowb];
                float e0,o0,e1,o1,e2,o2,e3,o3;
                up2(acc[0][cp], e0, o0); up2(acc[1][cp], e1, o1);
                up2(acc[2][cp], e2, o2); up2(acc[3][cp], e3, o3);
                float te, to;
                te = e0 * w1e; p0 += te; p0 = fmaf(-(te * he.x), he.x, p0);
                to = o0 * w1o; p0 += to; p0 = fmaf(-(to * ho.x), ho.x, p0);
                te = e1 * w1e; p1 += te; p1 = fmaf(-(te * he.y), he.y, p1);
                to = o1 * w1o; p1 += to; p1 = fmaf(-(to * ho.y), ho.y, p1);
                te = e2 * w1e; p2 += te; p2 = fmaf(-(te * he.z), he.z, p2);
                to = o2 * w1o; p2 += to; p2 = fmaf(-(to * ho.z), ho.z, p2);
                te = e3 * w1e; p3 += te; p3 = fmaf(-(te * he.w), he.w, p3);
                to = o3 * w1o; p3 += to; p3 = fmaf(-(to * ho.w), ho.w, p3);
            }
            // reduce over the 4 column-threads (lanes cq=0..3 within each r-group)
            p0 += __shfl_xor_sync(0xffffffffu, p0, 1); p0 += __shfl_xor_sync(0xffffffffu, p0, 2);
            p1 += __shfl_xor_sync(0xffffffffu, p1, 1); p1 += __shfl_xor_sync(0xffffffffu, p1, 2);
            p2 += __shfl_xor_sync(0xffffffffu, p2, 1); p2 += __shfl_xor_sync(0xffffffffu, p2, 2);
            p3 += __shfl_xor_sync(0xffffffffu, p3, 1); p3 += __shfl_xor_sync(0xffffffffu, p3, 2);
            ldr0 = fmaf(dt, p0, ldr0);
            ldr1 = fmaf(dt, p1, ldr1);
            ldr2 = fmaf(dt, p2, ldr2);
            ldr3 = fmaf(dt, p3, ldr3);
        }
        __syncwarp();   // protect OH/OG before next step overwrites
    }

    // ---------------- output ----------------
    if (cq == 0) {
        #pragma unroll
        for (int i2 = 0; i2 < 4; i2++) {
            const int row = base + rowb + i2;
            if (row < n) {
                float v[8];
                #pragma unroll
                for (int d = 0; d < DD; d++) v[d] = dsm[OX + d * RPC + rowb + i2];
                *(float4*)&out[row * DD]     = make_float4(v[0], v[1], v[2], v[3]);
                *(float4*)&out[row * DD + 4] = make_float4(v[4], v[5], v[6], v[7]);
            }
        }
        const int row0 = base + rowb;
        if (row0 + 3 < n) {
            *(float4*)&out[n * DD + row0] = make_float4(ldr0, ldr1, ldr2, ldr3);
        } else {
            if (row0 < n)     out[n * DD + row0]     = ldr0;
            if (row0 + 1 < n) out[n * DD + row0 + 1] = ldr1;
            if (row0 + 2 < n) out[n * DD + row0 + 2] = ldr2;
            if (row0 + 3 < n) out[n * DD + row0 + 3] = ldr3;
        }
    }
}

extern "C" void kernel_launch(void* const* d_in, const int* in_sizes, int n_in,
                              void* d_out, int out_size) {
    const float* x0 = (const float*)d_in[0];
    const float* W1 = (const float*)d_in[1];
    const float* b1 = (const float*)d_in[2];
    const float* W2 = (const float*)d_in[3];
    const float* b2 = (const float*)d_in[4];
    const float* W3 = (const float*)d_in[5];
    const float* b3 = (const float*)d_in[6];
    const int* nsp = (n_in > 7) ? (const int*)d_in[7] : nullptr;

    cudaFuncSetAttribute(cnf_kernel,
                         cudaFuncAttributeMaxDynamicSharedMemorySize, SMEM_BYTES);

    int n = in_sizes[0] / DD;
    int blocks = (n + RPC - 1) / RPC;
    cnf_kernel<<<blocks, TPB, SMEM_BYTES>>>(x0, W1, b1, W2, b2, W3, b3, nsp,
                                            (float*)d_out, n);
}